// round 4
// baseline (speedup 1.0000x reference)
#include <cuda_runtime.h>
#include <stdint.h>

// ---------------- Problem constants ----------------
#define JJ      4
#define BB      8192
#define HH      100
#define TT      10
#define VV      11
#define BT      16
#define ROWS    64        // JJ*BT
#define NTHREADS 512
#define NBLOCKS (BB/BT)   // 512
#define STR     104       // hidden row stride (16B aligned rows)
#define WSZ     38400     // GRU weight slab floats; also attn slab (12800 A + 25600 W_w)

// ---------------- Device scratch ----------------
__device__ __align__(16) float g_H[(size_t)JJ*TT*BB*HH];   // [j][t][b][e]
// GRU Whh^T: [cg][kk4][tx][12] ; 12 = gate g(0..2) x u(0..3), col=cg*32+tx, k=kk4*4+u
__device__ __align__(16) float g_wenc[WSZ];
__device__ __align__(16) float g_wdec[WSZ];
// attn: [0,12800): A_wT as [cg][kk4][tx][4] (col=cg*32+tx out, k=f)
//       [12800,38400): W_wT two 100-k slabs [s][cg][kk4][tx][4]
__device__ __align__(16) float g_attw[WSZ];
__device__ __align__(16) float g_lenc[VV*300];  // [v][g*100+col] = Wih+bih (+bhh for r,z)
__device__ __align__(16) float g_ldec[VV*300];
__device__ __align__(16) float g_bnenc[128];    // bhh_n padded
__device__ __align__(16) float g_bndec[128];
__device__ __align__(16) float g_wbi[128];      // W_b padded

// ---------------- helpers ----------------
__device__ __forceinline__ float tanha(float x){
    float y; asm("tanh.approx.f32 %0, %1;" : "=f"(y) : "f"(x)); return y;
}
__device__ __forceinline__ float sigf(float x){ return 0.5f * tanha(0.5f * x) + 0.5f; }
__device__ __forceinline__ uint64_t pk2(float a){
    uint64_t r; asm("mov.b64 %0, {%1, %1};" : "=l"(r) : "f"(a)); return r;
}
__device__ __forceinline__ uint64_t pkpair(float a, float b){
    uint64_t r; asm("mov.b64 %0, {%1, %2};" : "=l"(r) : "f"(a), "f"(b)); return r;
}
__device__ __forceinline__ void upk(uint64_t v, float& a, float& b){
    asm("mov.b64 {%0, %1}, %2;" : "=f"(a), "=f"(b) : "l"(v));
}
__device__ __forceinline__ void ffma2(uint64_t& d, uint64_t a, uint64_t b){
    asm("fma.rn.f32x2 %0, %1, %2, %0;" : "+l"(d) : "l"(a), "l"(b));
}
__device__ __forceinline__ float comp4(const float4& v, int u){
    return u==0 ? v.x : (u==1 ? v.y : (u==2 ? v.z : v.w));
}

// ---------------- Prep kernel ----------------
__global__ void prep_kernel(const float* __restrict__ eWih, const float* __restrict__ eWhh,
                            const float* __restrict__ ebih, const float* __restrict__ ebhh,
                            const float* __restrict__ dWih, const float* __restrict__ dWhh,
                            const float* __restrict__ dbih, const float* __restrict__ dbhh,
                            const float* __restrict__ Ww,   const float* __restrict__ Aw,
                            const float* __restrict__ Wb)
{
    int i = blockIdx.x * blockDim.x + threadIdx.x;
    if (i < WSZ) {                               // GRU Whh^T, col-group layout
        int cg = i / 9600, r1 = i % 9600;
        int kk4 = r1 / 384, r2 = r1 % 384;
        int tx = r2 / 12, gu = r2 % 12;
        int g = gu / 4, u = gu % 4;
        int col = cg*32 + tx, k = kk4*4 + u;
        float we = 0.f, wd = 0.f;
        if (col < HH) {
            we = eWhh[(g*HH + col)*HH + k];
            wd = dWhh[(g*HH + col)*HH + k];
        }
        g_wenc[i] = we; g_wdec[i] = wd;
    }
    if (i < WSZ) {                               // attention weights
        float v = 0.f;
        if (i < 12800) {                         // A_wT col-group layout
            int cg = i / 3200, r = i % 3200;
            int kk4 = r / 128, r2 = r % 128;
            int tx = r2 / 4, u = r2 % 4;
            int col = cg*32 + tx, f = kk4*4 + u;
            if (col < HH) v = Aw[col*HH + f];
        } else {
            int i2 = i - 12800;
            int s = i2 / 12800, r3 = i2 % 12800;
            int cg = r3 / 3200, r = r3 % 3200;
            int kk4 = r / 128, r2 = r % 128;
            int tx = r2 / 4, u = r2 % 4;
            int col = cg*32 + tx, k = kk4*4 + u;
            if (col < HH) v = Ww[col*200 + s*100 + k];
        }
        g_attw[i] = v;
    }
    if (i < VV*300) {                            // one-hot LUT (+bih, +bhh for r,z)
        int v = i / 300, rem = i % 300, g = rem / 100, col = rem % 100;
        int gc = g*HH + col;
        float extra_e = (g < 2) ? ebhh[gc] : 0.f;
        float extra_d = (g < 2) ? dbhh[gc] : 0.f;
        g_lenc[i] = eWih[gc*VV + v] + ebih[gc] + extra_e;
        g_ldec[i] = dWih[gc*VV + v] + dbih[gc] + extra_d;
    }
    if (i < 128) {
        g_bnenc[i] = (i < HH) ? ebhh[200 + i] : 0.f;
        g_bndec[i] = (i < HH) ? dbhh[200 + i] : 0.f;
        g_wbi[i]   = (i < HH) ? Wb[i] : 0.f;
    }
}

// ---------------- smem layout (floats) ----------------
#define OFF_W     0          // 38400
#define OFF_B0    38400      // 6656
#define OFF_B1    45056      // 6656
#define OFF_LUT   51712      // 3300
#define OFF_BN    55012      // 128
#define OFF_WBI   55140      // 128
#define OFF_M     55268      // 1664 (16*104)
#define OFF_SC    56932      // 640
#define OFF_VB    57572      // 12
#define OFF_LG    57584      // 192
#define OFF_TOK   57776      // 64 ints
#define OFF_SCORE 57840      // 16
#define SMEM_FLOATS 57856
#define SMEM_BYTES (SMEM_FLOATS*4)   // 231424

__device__ __forceinline__ void copy4(float* dst, const float* src, int n4, int tid){
    float4* d = (float4*)dst; const float4* s = (const float4*)src;
    for (int i = tid; i < n4; i += NTHREADS) d[i] = s[i];
}

// ---- GRU step: warp (rg,cg) computes 16 rows x (3 gates x 32 cols) ----
__device__ __forceinline__ void gru_step(const float* __restrict__ s_w,
                                         const float* __restrict__ s_bn,
                                         const float* __restrict__ s_lut,
                                         const int*   __restrict__ s_tok,
                                         const float* __restrict__ s_hin,
                                         float*       __restrict__ s_hout,
                                         int rg, int cg, int tx,
                                         bool writeH, int t, int b0)
{
    const int c = cg*32 + tx;
    uint64_t acc[8][3];
    {
        uint64_t bn2 = pk2(s_bn[c]);
        #pragma unroll
        for (int p = 0; p < 8; p++) { acc[p][0] = 0ull; acc[p][1] = 0ull; acc[p][2] = bn2; }
    }
    const float4* wp = (const float4*)(s_w + cg*9600);
    const float* hin = s_hin + rg*16*STR;
    #pragma unroll 1
    for (int kk4 = 0; kk4 < 25; kk4++) {
        float4 w0 = wp[kk4*96 + tx*3 + 0];
        float4 w1 = wp[kk4*96 + tx*3 + 1];
        float4 w2 = wp[kk4*96 + tx*3 + 2];
        #pragma unroll
        for (int half = 0; half < 2; half++) {
            float4 h4[8];
            #pragma unroll
            for (int i = 0; i < 8; i++)
                h4[i] = *(const float4*)(hin + (half*8 + i)*STR + kk4*4);
            #pragma unroll
            for (int u = 0; u < 4; u++) {
                uint64_t W0 = pk2(comp4(w0, u));
                uint64_t W1 = pk2(comp4(w1, u));
                uint64_t W2 = pk2(comp4(w2, u));
                #pragma unroll
                for (int p = 0; p < 4; p++) {
                    uint64_t h2 = pkpair(comp4(h4[2*p], u), comp4(h4[2*p+1], u));
                    int pi = half*4 + p;
                    ffma2(acc[pi][0], h2, W0);
                    ffma2(acc[pi][1], h2, W1);
                    ffma2(acc[pi][2], h2, W2);
                }
            }
        }
    }
    if (c < HH) {
        #pragma unroll
        for (int p = 0; p < 8; p++) {
            float a0,a1,b0v,b1v,n0,n1;
            upk(acc[p][0], a0, a1);
            upk(acc[p][1], b0v, b1v);
            upk(acc[p][2], n0, n1);
            #pragma unroll
            for (int hh = 0; hh < 2; hh++) {
                int bi = 2*p + hh;
                int r = rg*16 + bi;
                float av = hh ? a1 : a0;
                float bv = hh ? b1v : b0v;
                float nv = hh ? n1 : n0;
                const float* lutb = s_lut + s_tok[r]*300;
                float rgt = sigf(lutb[c]       + av);
                float zgt = sigf(lutb[100 + c] + bv);
                float ngt = tanha(lutb[200 + c] + rgt*nv);
                float hp  = s_hin[r*STR + c];
                float hv  = ngt + zgt*(hp - ngt);
                s_hout[r*STR + c] = hv;
                if (writeH)
                    g_H[(((size_t)(rg*TT + t))*BB + (b0 + bi))*HH + c] = hv;
            }
        }
    }
}

// ---- 100-k GEMM slab, single output gate: acc[8] += in @ W ----
__device__ __forceinline__ void gemm100b(uint64_t acc[8],
                                         const float* __restrict__ hin,   // already + rg*16*STR
                                         const float4* __restrict__ wp,   // per-cg slab base
                                         int tx)
{
    #pragma unroll 1
    for (int kk4 = 0; kk4 < 25; kk4++) {
        float4 w = wp[kk4*32 + tx];
        #pragma unroll
        for (int half = 0; half < 2; half++) {
            float4 h4[8];
            #pragma unroll
            for (int i = 0; i < 8; i++)
                h4[i] = *(const float4*)(hin + (half*8 + i)*STR + kk4*4);
            #pragma unroll
            for (int u = 0; u < 4; u++) {
                uint64_t W = pk2(comp4(w, u));
                #pragma unroll
                for (int p = 0; p < 4; p++) {
                    uint64_t h2 = pkpair(comp4(h4[2*p], u), comp4(h4[2*p+1], u));
                    ffma2(acc[half*4 + p], h2, W);
                }
            }
        }
    }
}

__global__ void __launch_bounds__(NTHREADS, 1)
robustfill_kernel(const int* __restrict__ inputs, const int* __restrict__ target,
                  const float* __restrict__ Vw, const float* __restrict__ Vb,
                  float* __restrict__ out)
{
    extern __shared__ float sm[];
    float* s_w    = sm + OFF_W;
    float* s_b0   = sm + OFF_B0;
    float* s_b1   = sm + OFF_B1;
    float* s_lut  = sm + OFF_LUT;
    float* s_bn   = sm + OFF_BN;
    float* s_wbi  = sm + OFF_WBI;
    float* s_m    = sm + OFF_M;
    float* s_sc   = sm + OFF_SC;
    float* s_vb   = sm + OFF_VB;
    float* s_lg   = sm + OFF_LG;
    int*   s_tok  = (int*)(sm + OFF_TOK);
    float* s_scr  = sm + OFF_SCORE;

    const int tid = threadIdx.x;
    const int wid = tid >> 5, tx = tid & 31;
    const int rg = wid >> 2, cg = wid & 3;
    const int c  = cg*32 + tx;
    const int b0 = blockIdx.x * BT;

    // ---- initial staging ----
    copy4(s_w,   g_wenc,  WSZ/4,    tid);
    copy4(s_lut, g_lenc,  VV*300/4, tid);
    copy4(s_bn,  g_bnenc, 32,       tid);
    copy4(s_wbi, g_wbi,   32,       tid);
    if (tid < VV) s_vb[tid] = Vb[tid];
    if (tid < BT) s_scr[tid] = 0.f;
    for (int i = tid; i < ROWS*STR/4; i += NTHREADS)
        *(float4*)(s_b0 + 4*i) = make_float4(0.f, 0.f, 0.f, 0.f);
    __syncthreads();

    float* hcur = s_b0;
    float* hnx  = s_b1;

    // ================= ENCODER =================
    for (int t = 0; t < TT; t++) {
        if (tid < ROWS) s_tok[tid] = inputs[((tid >> 4)*TT + t)*BB + b0 + (tid & 15)];
        __syncthreads();
        gru_step(s_w, s_bn, s_lut, s_tok, hcur, hnx, rg, cg, tx, true, t, b0);
        __syncthreads();
        float* tmp = hcur; hcur = hnx; hnx = tmp;
    }

    // ================= P0 with decoder weights =================
    copy4(s_w,   g_wdec,  WSZ/4,    tid);
    copy4(s_lut, g_ldec,  VV*300/4, tid);
    copy4(s_bn,  g_bndec, 32,       tid);
    if (tid < ROWS) s_tok[tid] = VV - 1;
    __syncthreads();
    gru_step(s_w, s_bn, s_lut, s_tok, hcur, hnx, rg, cg, tx, false, 0, b0);
    __syncthreads();
    { float* tmp = hcur; hcur = hnx; hnx = tmp; }   // hcur = P

    // ================= DECODER =================
    for (int t = 0; t < TT; t++) {
        if (tid < ROWS) s_tok[tid] = target[t*BB + b0 + (tid & 15)];
        copy4(s_w, g_attw, WSZ/4, tid);          // attA + W_wT
        __syncthreads();

        // ---- D2: AP[r][e] = sum_f A_w[e][f] * P[r][f] -> hnx ----
        {
            uint64_t acc[8];
            #pragma unroll
            for (int p = 0; p < 8; p++) acc[p] = 0ull;
            gemm100b(acc, hcur + rg*16*STR, (const float4*)(s_w + cg*3200), tx);
            if (c < HH) {
                #pragma unroll
                for (int p = 0; p < 8; p++) {
                    float v0, v1; upk(acc[p], v0, v1);
                    hnx[(rg*16 + 2*p    )*STR + c] = v0;
                    hnx[(rg*16 + 2*p + 1)*STR + c] = v1;
                }
            }
        }
        __syncthreads();

        // ---- D3: scores[r][q] = sum_e H[j,q,b,e] * AP[r][e] ----
        for (int task = tid; task < ROWS*TT; task += NTHREADS) {
            int r = task / TT, q = task % TT;
            int j = r >> 4, b = b0 + (r & 15);
            const float4* Hp = (const float4*)(g_H + (((size_t)(j*TT + q))*BB + b)*HH);
            const float4* ap = (const float4*)(hnx + r*STR);
            float s = 0.f;
            #pragma unroll
            for (int e4 = 0; e4 < 25; e4++) {
                float4 h4 = Hp[e4], a4 = ap[e4];
                s += h4.x*a4.x + h4.y*a4.y + h4.z*a4.z + h4.w*a4.w;
            }
            s_sc[r*TT + q] = s;
        }
        __syncthreads();

        // ---- D4: log_softmax over q ----
        if (tid < ROWS) {
            float mx = -1e30f;
            #pragma unroll
            for (int q = 0; q < TT; q++) mx = fmaxf(mx, s_sc[tid*TT + q]);
            float se = 0.f;
            #pragma unroll
            for (int q = 0; q < TT; q++) se += __expf(s_sc[tid*TT + q] - mx);
            float lse = mx + __logf(se);
            #pragma unroll
            for (int q = 0; q < TT; q++) s_sc[tid*TT + q] -= lse;
        }
        __syncthreads();

        // ---- D5: c[r][e] = sum_q logs[r][q] * H[j,q,b,e] -> hnx ----
        for (int task = tid; task < ROWS*50; task += NTHREADS) {
            int r = task / 50, e2 = task % 50;
            int j = r >> 4, b = b0 + (r & 15);
            float ax = 0.f, ay = 0.f;
            #pragma unroll
            for (int q = 0; q < TT; q++) {
                float lg = s_sc[r*TT + q];
                float2 h2 = *(const float2*)(g_H + (((size_t)(j*TT + q))*BB + b)*HH + e2*2);
                ax = fmaf(lg, h2.x, ax); ay = fmaf(lg, h2.y, ay);
            }
            *(float2*)(hnx + r*STR + e2*2) = make_float2(ax, ay);
        }
        __syncthreads();

        // ---- D6: fc = tanh(W_w @ [P, c] + W_b); m = max over j ----
        {
            uint64_t acc[8];
            {
                uint64_t wb2 = pk2(s_wbi[c]);
                #pragma unroll
                for (int p = 0; p < 8; p++) acc[p] = wb2;
            }
            gemm100b(acc, hcur + rg*16*STR, (const float4*)(s_w + 12800 + cg*3200), tx);
            gemm100b(acc, hnx  + rg*16*STR, (const float4*)(s_w + 25600 + cg*3200), tx);
            float fc[16];
            #pragma unroll
            for (int p = 0; p < 8; p++) {
                float v0, v1; upk(acc[p], v0, v1);
                fc[2*p]   = tanha(v0);
                fc[2*p+1] = tanha(v1);
            }
            for (int jj = 0; jj < JJ; jj++) {
                if (rg == jj && c < HH) {
                    #pragma unroll
                    for (int bi = 0; bi < 16; bi++) {
                        float* mp = s_m + bi*STR + c;
                        if (jj == 0) *mp = fc[bi];
                        else         *mp = fmaxf(*mp, fc[bi]);
                    }
                }
                __syncthreads();
            }
        }

        // ---- D7: logits (V_w from global/L2); overlap dec-weight restage ----
        if (tid < BT*VV) {
            int bi = tid / VV, v = tid % VV;
            float a = s_vb[v];
            const float4* vr = (const float4*)(Vw + v*HH);
            const float4* mr = (const float4*)(s_m + bi*STR);
            #pragma unroll
            for (int e = 0; e < 25; e++) {
                float4 m4 = mr[e], v4 = vr[e];
                a = fmaf(m4.x, v4.x, fmaf(m4.y, v4.y, fmaf(m4.z, v4.z, fmaf(m4.w, v4.w, a))));
            }
            s_lg[bi*12 + v] = a;
        }
        copy4(s_w, g_wdec, WSZ/4, tid);          // restage decoder GRU weights
        __syncthreads();

        // ---- score + D9: P_new = GRU(target_onehot, c) ----
        if (tid < BT) {
            float mx = -1e30f;
            #pragma unroll
            for (int v = 0; v < VV; v++) mx = fmaxf(mx, s_lg[tid*12 + v]);
            float se = 0.f;
            #pragma unroll
            for (int v = 0; v < VV; v++) se += __expf(s_lg[tid*12 + v] - mx);
            float lse = mx + __logf(se);
            s_scr[tid] += s_lg[tid*12 + s_tok[tid]] - lse;
        }
        gru_step(s_w, s_bn, s_lut, s_tok, hnx, hcur, rg, cg, tx, false, 0, b0);
        __syncthreads();
    }

    if (tid < BT) out[b0 + tid] = s_scr[tid];
}

// ---------------- Launch ----------------
extern "C" void kernel_launch(void* const* d_in, const int* in_sizes, int n_in,
                              void* d_out, int out_size)
{
    const int*   inputs  = (const int*)  d_in[0];
    const int*   target  = (const int*)  d_in[1];
    const float* eWih    = (const float*)d_in[2];
    const float* eWhh    = (const float*)d_in[3];
    const float* ebih    = (const float*)d_in[4];
    const float* ebhh    = (const float*)d_in[5];
    const float* dWih    = (const float*)d_in[6];
    const float* dWhh    = (const float*)d_in[7];
    const float* dbih    = (const float*)d_in[8];
    const float* dbhh    = (const float*)d_in[9];
    const float* Ww      = (const float*)d_in[10];
    const float* Wb      = (const float*)d_in[11];
    const float* Vw      = (const float*)d_in[12];
    const float* Vb      = (const float*)d_in[13];
    const float* Aw      = (const float*)d_in[14];
    float* out = (float*)d_out;

    static int smem_set = 0;
    if (!smem_set) {
        cudaFuncSetAttribute(robustfill_kernel,
                             cudaFuncAttributeMaxDynamicSharedMemorySize, SMEM_BYTES);
        smem_set = 1;
    }

    prep_kernel<<<(WSZ + 255)/256, 256>>>(eWih, eWhh, ebih, ebhh,
                                          dWih, dWhh, dbih, dbhh, Ww, Aw, Wb);
    robustfill_kernel<<<NBLOCKS, NTHREADS, SMEM_BYTES>>>(inputs, target, Vw, Vb, out);
}